// round 14
// baseline (speedup 1.0000x reference)
#include <cuda_runtime.h>
#include <cuda_fp16.h>
#include <math.h>

// Problem constants (fixed by the dataset)
#define NN  50000
#define EE  800000
#define FIN 128
#define HH  128
#define CC  64

#define SCAN_NB 196   // 196 * 256 = 50176 >= NN

// ---------------- device scratch (feature tensors in half2 words) -------------------
__device__ int      g_icnt[NN];
__device__ int      g_rowp[NN + 1];
__device__ int      g_cur [NN];
__device__ int      g_srcs[EE];
__device__ unsigned long long g_desc[SCAN_NB];   // decoupled-lookback descriptors
__device__ unsigned g_xh  [NN * 64];   // x           (half2)
__device__ unsigned g_aggh[NN * 64];   // mean_aggr(x)(half2)
__device__ unsigned g_t2h [NN * 32];   // t2          (half2)
__device__ float    g_r2  [NN * CC];   // h2 @ W2_r^T (f32)
__device__ unsigned g_wh0[128 * 128];  // [W1_l|W1_r] rows of 256 halfs
__device__ unsigned g_wh1[128 * 128];  // Wl1         rows of 256 halfs
__device__ unsigned g_wh2[128 * 64];   // [W2_l;W2_r] rows of 128 halfs

__device__ __forceinline__ unsigned pack_h2(float lo, float hi) {
    __half2 h = __floats2half2_rn(lo, hi);
    return *(unsigned*)&h;
}
__device__ __forceinline__ float2 h2f2(unsigned u) {
    return __half22float2(*(__half2*)&u);
}

// ---------------- prep: x -> fp16, weights -> fp16, zero counters/descriptors ----------
__global__ void k_prep(const float* __restrict__ x,
                       const float* __restrict__ W1_l, const float* __restrict__ W1_r,
                       const float* __restrict__ Wl1,
                       const float* __restrict__ W2_l, const float* __restrict__ W2_r) {
    int i = blockIdx.x * blockDim.x + threadIdx.x;   // uint2 unit = 4 floats
    if (i < NN * 32) {
        float4 v = ((const float4*)x)[i];
        ((uint2*)g_xh)[i] = make_uint2(pack_h2(v.x, v.y), pack_h2(v.z, v.w));
    }
    if (i < NN) g_icnt[i] = 0;
    if (i < SCAN_NB) g_desc[i] = 0ull;
    if (i < 128 * 128) {
        int j = i >> 7, k = (i & 127) * 2;
        float a = (k < 128) ? W1_l[j * 128 + k]     : W1_r[j * 128 + k - 128];
        float b = (k < 128) ? W1_l[j * 128 + k + 1] : W1_r[j * 128 + k + 1 - 128];
        g_wh0[i] = pack_h2(a, b);
        g_wh1[i] = pack_h2(Wl1[j * 256 + k], Wl1[j * 256 + k + 1]);
    }
    if (i < 128 * 64) {
        int j = i >> 6, k = (i & 63) * 2;
        float a = (j < 64) ? W2_l[j * 128 + k]     : W2_r[(j - 64) * 128 + k];
        float b = (j < 64) ? W2_l[j * 128 + k + 1] : W2_r[(j - 64) * 128 + k + 1];
        g_wh2[i] = pack_h2(a, b);
    }
}

// ---------------- degree count: 4 edges/thread ----------------------------------------
__global__ void k_count(const int* __restrict__ ei) {
    int e0 = (blockIdx.x * blockDim.x + threadIdx.x) * 4;
    if (e0 >= EE) return;
    int4 d = *(const int4*)(ei + EE + e0);
    atomicAdd(&g_icnt[d.x], 1);
    atomicAdd(&g_icnt[d.y], 1);
    atomicAdd(&g_icnt[d.z], 1);
    atomicAdd(&g_icnt[d.w], 1);
}

// ---------------- single-pass decoupled-lookback exclusive scan -------------------------
// desc state in bits [32..]: 0 = invalid, 1 = aggregate ready, 2 = inclusive prefix ready
__global__ void k_scan() {
    __shared__ int sm[256];
    __shared__ int s_base;
    const int t = threadIdx.x;
    const int b = blockIdx.x;
    const int i = b * 256 + t;
    int v = (i < NN) ? g_icnt[i] : 0;
    sm[t] = v;
    __syncthreads();
#pragma unroll
    for (int o = 1; o < 256; o <<= 1) {
        int u = (t >= o) ? sm[t - o] : 0;
        __syncthreads();
        sm[t] += u;
        __syncthreads();
    }
    const int total = sm[255];
    if (t == 0) {
        if (b == 0) {
            __threadfence();
            atomicExch(&g_desc[0], (2ull << 32) | (unsigned)total);
            s_base = 0;
        } else {
            __threadfence();
            atomicExch(&g_desc[b], (1ull << 32) | (unsigned)total);
            int running = 0;
            int idx = b - 1;
            while (true) {
                unsigned long long d = atomicAdd(&g_desc[idx], 0ull);
                unsigned st = (unsigned)(d >> 32);
                if (st == 0) continue;                 // not yet published
                running += (int)(unsigned)(d & 0xffffffffull);
                if (st == 2) break;                    // found inclusive prefix
                idx--;
            }
            __threadfence();
            atomicExch(&g_desc[b], (2ull << 32) | (unsigned)(running + total));
            s_base = running;
        }
    }
    __syncthreads();
    int ex = sm[t] - v + s_base;
    if (i < NN) { g_rowp[i] = ex; g_cur[i] = ex; }
    if (i == NN) g_rowp[NN] = ex;   // == EE
}

// ---------------- bin: srcs sorted by dst (4 edges/thread) -----------------------------
__global__ void k_bin(const int* __restrict__ ei) {
    int e0 = (blockIdx.x * blockDim.x + threadIdx.x) * 4;
    if (e0 >= EE) return;
    int4 s = *(const int4*)(ei + e0);
    int4 d = *(const int4*)(ei + EE + e0);
    int p0 = atomicAdd(&g_cur[d.x], 1);
    int p1 = atomicAdd(&g_cur[d.y], 1);
    int p2 = atomicAdd(&g_cur[d.z], 1);
    int p3 = atomicAdd(&g_cur[d.w], 1);
    g_srcs[p0] = s.x; g_srcs[p1] = s.y; g_srcs[p2] = s.z; g_srcs[p3] = s.w;
}

// ---------------- layer-1 mean aggregation: warp/node, unroll-8 ------------------------
__global__ void k_aggr1() {
    int node = (blockIdx.x * blockDim.x + threadIdx.x) >> 5;
    int lane = threadIdx.x & 31;
    if (node >= NN) return;
    int beg = g_rowp[node], end = g_rowp[node + 1];
    float4 a0 = make_float4(0.f, 0.f, 0.f, 0.f);
    float4 a1 = make_float4(0.f, 0.f, 0.f, 0.f);
    float4 a2 = make_float4(0.f, 0.f, 0.f, 0.f);
    float4 a3 = make_float4(0.f, 0.f, 0.f, 0.f);
    int i = beg;
    for (; i + 7 < end; i += 8) {
        int idx[8];
#pragma unroll
        for (int q = 0; q < 8; q++) idx[q] = __ldg(&g_srcs[i + q]);
        uint2 u[8];
#pragma unroll
        for (int q = 0; q < 8; q++)
            u[q] = *(const uint2*)(g_xh + (size_t)idx[q] * 64 + lane * 2);
#pragma unroll
        for (int q = 0; q < 8; q += 4) {
            float2 p0 = h2f2(u[q+0].x), p1 = h2f2(u[q+0].y);
            float2 q0 = h2f2(u[q+1].x), q1 = h2f2(u[q+1].y);
            float2 r0 = h2f2(u[q+2].x), r1 = h2f2(u[q+2].y);
            float2 t0 = h2f2(u[q+3].x), t1 = h2f2(u[q+3].y);
            a0.x += p0.x; a0.y += p0.y; a0.z += p1.x; a0.w += p1.y;
            a1.x += q0.x; a1.y += q0.y; a1.z += q1.x; a1.w += q1.y;
            a2.x += r0.x; a2.y += r0.y; a2.z += r1.x; a2.w += r1.y;
            a3.x += t0.x; a3.y += t0.y; a3.z += t1.x; a3.w += t1.y;
        }
    }
    for (; i < end; i++) {
        int s0 = __ldg(&g_srcs[i]);
        uint2 u0 = *(const uint2*)(g_xh + (size_t)s0 * 64 + lane * 2);
        float2 p0 = h2f2(u0.x), p1 = h2f2(u0.y);
        a0.x += p0.x; a0.y += p0.y; a0.z += p1.x; a0.w += p1.y;
    }
    float inv = 1.0f / fmaxf((float)(end - beg), 1.0f);
    uint2 o;
    o.x = pack_h2((a0.x + a1.x + a2.x + a3.x) * inv, (a0.y + a1.y + a2.y + a3.y) * inv);
    o.y = pack_h2((a0.z + a1.z + a2.z + a3.z) * inv, (a0.w + a1.w + a2.w + a3.w) * inv);
    *(uint2*)(g_aggh + (size_t)node * 64 + lane * 2) = o;
}

// ---------------- fp16 MMA helper ------------------------------------------------------
#define MMA_F16(d, a, b)                                                          \
    asm volatile("mma.sync.aligned.m16n8k16.row.col.f32.f16.f16.f32 "             \
                 "{%0,%1,%2,%3}, {%4,%5,%6,%7}, {%8,%9}, {%0,%1,%2,%3};"          \
                 : "+f"(d[0]), "+f"(d[1]), "+f"(d[2]), "+f"(d[3])                 \
                 : "r"(a[0]), "r"(a[1]), "r"(a[2]), "r"(a[3]),                    \
                   "r"(b[0]), "r"(b[1]))

// ---------------- FUSED 3-GEMM kernel (proven R11 structure) ----------------------------
// Per CTA: 128 nodes. A operand lives in smem for the whole kernel:
//   XA words 0..63  = agg (later h, then h2), 64..127 = x (resident)
// GEMM0: [agg|x]@wh0^T -> +b1, L2-norm, relu -> h   -> XA[0..63]
// GEMM1: [x|h] @wh1^T -> +bl1, relu          -> h2  -> XA[0..63]
// GEMM2: h2    @wh2^T -> t2 (half) + r2 (f32)
#define RSX 132   // XA row stride in half2 words (132 % 32 == 4 -> conflict-free)
#define RSW 36    // Ws row stride in half2 words
#define FUSED_SMEM ((128 * RSX + 128 * RSW) * 4 + 512 * 4 + 256 * 4)

__global__ __launch_bounds__(256)
void k_fused(const float* __restrict__ b1, const float* __restrict__ bl1) {
    extern __shared__ unsigned smem[];
    unsigned* XA  = smem;                       // 128*132 words
    unsigned* Ws  = smem + 128 * RSX;           // 128*36 words
    float*    rss = (float*)(Ws + 128 * RSW);   // 512 floats
    float*    bsm = rss + 512;                  // 256 floats: b1 | bl1

    const int tid  = threadIdx.x;
    const int lane = tid & 31;
    const int w    = tid >> 5;
    const int wm   = w & 1;        // 0..1 (64 rows each)
    const int wn   = w >> 1;       // 0..3 (32 cols each)
    const int qid  = lane >> 2;    // 0..7
    const int tig  = lane & 3;     // 0..3
    const int m0   = blockIdx.x * 128;

    bsm[tid] = (tid < 128) ? b1[tid] : bl1[tid - 128];

    // ---- fill XA: words 0..63 = agg, 64..127 = x ----
#pragma unroll
    for (int p = 0; p < 16; p++) {
        int f    = tid + p * 256;        // 0..4095
        int row  = f >> 5;               // 0..127
        int word = (f & 31) * 4;         // uint4-aligned word 0..124
        int gm   = min(m0 + row, NN - 1);
        uint4 v = (word < 64)
            ? *(const uint4*)(g_aggh + (size_t)gm * 64 + word)
            : *(const uint4*)(g_xh   + (size_t)gm * 64 + (word - 64));
        *(uint4*)(&XA[row * RSX + word]) = v;
    }

    // ---- weight chunk streaming ----
    uint4 rw4[4];
    auto loadW = [&](int idx) {   // flat chunk idx 0..9
        const unsigned* base; int WR, off;
        if (idx < 4)      { base = g_wh0; WR = 128; off = idx * 32; }
        else if (idx < 8) { base = g_wh1; WR = 128; off = (idx - 4) * 32; }
        else              { base = g_wh2; WR = 64;  off = (idx - 8) * 32; }
#pragma unroll
        for (int p = 0; p < 4; p++) {
            int f = tid + p * 256;
            int j = f >> 3, seg = f & 7;
            rw4[p] = *(const uint4*)(base + j * WR + off + seg * 4);
        }
    };
    auto storeW = [&]() {
#pragma unroll
        for (int p = 0; p < 4; p++) {
            int f = tid + p * 256;
            int j = f >> 3, seg = f & 7;
            *(uint4*)(&Ws[j * RSW + seg * 4]) = rw4[p];
        }
    };

    float acc[4][4][4];
    auto resetAcc = [&]() {
#pragma unroll
        for (int mt = 0; mt < 4; mt++)
#pragma unroll
            for (int nt = 0; nt < 4; nt++)
#pragma unroll
                for (int c = 0; c < 4; c++) acc[mt][nt][c] = 0.f;
    };

    int widx = 0;
    loadW(0); widx = 1;

    auto runChunks = [&](int nch, int gsel) {
        for (int c = 0; c < nch; c++) {
            __syncthreads();
            storeW();
            __syncthreads();
            if (widx < 10) { loadW(widx); widx++; }
            int offA = (gsel == 1) ? ((c < 2) ? 64 + c * 32 : (c - 2) * 32)
                                   : c * 32;
#pragma unroll
            for (int ks = 0; ks < 4; ks++) {
                const int kb = ks * 8;
                unsigned a[4][4];
#pragma unroll
                for (int mt = 0; mt < 4; mt++) {
                    int r0 = wm * 64 + mt * 16 + qid;
                    a[mt][0] = XA[r0 * RSX + offA + kb + tig];
                    a[mt][1] = XA[(r0 + 8) * RSX + offA + kb + tig];
                    a[mt][2] = XA[r0 * RSX + offA + kb + tig + 4];
                    a[mt][3] = XA[(r0 + 8) * RSX + offA + kb + tig + 4];
                }
                unsigned b[4][2];
#pragma unroll
                for (int nt = 0; nt < 4; nt++) {
                    int c0 = wn * 32 + nt * 8 + qid;
                    b[nt][0] = Ws[c0 * RSW + kb + tig];
                    b[nt][1] = Ws[c0 * RSW + kb + tig + 4];
                }
#pragma unroll
                for (int mt = 0; mt < 4; mt++)
#pragma unroll
                    for (int nt = 0; nt < 4; nt++)
                        MMA_F16(acc[mt][nt], a[mt], b[nt]);
            }
        }
    };

    // ================= GEMM0: [agg|x] @ wh0^T =================
    resetAcc();
    runChunks(4, 0);

    // epilogue0: +b1, L2 row-norm, relu, h -> XA words 0..63
    {
#pragma unroll
        for (int nt = 0; nt < 4; nt++) {
            float bx = bsm[wn * 32 + nt * 8 + tig * 2];
            float by = bsm[wn * 32 + nt * 8 + tig * 2 + 1];
#pragma unroll
            for (int mt = 0; mt < 4; mt++) {
                acc[mt][nt][0] += bx; acc[mt][nt][1] += by;
                acc[mt][nt][2] += bx; acc[mt][nt][3] += by;
            }
        }
        float ssl[4][2];
#pragma unroll
        for (int mt = 0; mt < 4; mt++) {
            float s0 = 0.f, s1 = 0.f;
#pragma unroll
            for (int nt = 0; nt < 4; nt++) {
                s0 += acc[mt][nt][0] * acc[mt][nt][0] + acc[mt][nt][1] * acc[mt][nt][1];
                s1 += acc[mt][nt][2] * acc[mt][nt][2] + acc[mt][nt][3] * acc[mt][nt][3];
            }
            s0 += __shfl_xor_sync(0xffffffffu, s0, 1);
            s0 += __shfl_xor_sync(0xffffffffu, s0, 2);
            s1 += __shfl_xor_sync(0xffffffffu, s1, 1);
            s1 += __shfl_xor_sync(0xffffffffu, s1, 2);
            ssl[mt][0] = s0; ssl[mt][1] = s1;
        }
        if (tig == 0) {
#pragma unroll
            for (int mt = 0; mt < 4; mt++) {
                int r0 = wm * 64 + mt * 16 + qid;
                rss[(r0)     * 4 + wn] = ssl[mt][0];
                rss[(r0 + 8) * 4 + wn] = ssl[mt][1];
            }
        }
        __syncthreads();   // all GEMM0 MMAs done before XA[0..63] overwrite
#pragma unroll
        for (int mt = 0; mt < 4; mt++) {
#pragma unroll
            for (int h = 0; h < 2; h++) {
                int r = wm * 64 + mt * 16 + qid + h * 8;
                float ss = rss[r * 4 + 0] + rss[r * 4 + 1] + rss[r * 4 + 2] + rss[r * 4 + 3];
                float scl = 1.0f / fmaxf(sqrtf(ss), 1e-12f);
#pragma unroll
                for (int nt = 0; nt < 4; nt++) {
                    float ox = fmaxf(acc[mt][nt][h * 2 + 0] * scl, 0.f);
                    float oy = fmaxf(acc[mt][nt][h * 2 + 1] * scl, 0.f);
                    XA[r * RSX + wn * 16 + nt * 4 + tig] = pack_h2(ox, oy);
                }
            }
        }
    }

    // ================= GEMM1: [x|h] @ wh1^T =================
    resetAcc();
    runChunks(4, 1);

    // epilogue1: +bl1, relu, h2 -> XA words 0..63
    __syncthreads();   // all GEMM1 MMAs done before overwriting h
    {
#pragma unroll
        for (int mt = 0; mt < 4; mt++) {
#pragma unroll
            for (int h = 0; h < 2; h++) {
                int r = wm * 64 + mt * 16 + qid + h * 8;
#pragma unroll
                for (int nt = 0; nt < 4; nt++) {
                    float bx = bsm[128 + wn * 32 + nt * 8 + tig * 2];
                    float by = bsm[128 + wn * 32 + nt * 8 + tig * 2 + 1];
                    float ox = fmaxf(acc[mt][nt][h * 2 + 0] + bx, 0.f);
                    float oy = fmaxf(acc[mt][nt][h * 2 + 1] + by, 0.f);
                    XA[r * RSX + wn * 16 + nt * 4 + tig] = pack_h2(ox, oy);
                }
            }
        }
    }

    // ================= GEMM2: h2 @ wh2^T =================
    resetAcc();
    runChunks(2, 2);

    // epilogue2: cols 0..63 -> t2 (half2), 64..127 -> r2 (f32)
    {
        const bool is_t2 = (wn < 2);
        const int coff0 = is_t2 ? wn * 32 : (wn - 2) * 32;
#pragma unroll
        for (int mt = 0; mt < 4; mt++) {
#pragma unroll
            for (int h = 0; h < 2; h++) {
                int gm = m0 + wm * 64 + mt * 16 + qid + h * 8;
                if (gm < NN) {
#pragma unroll
                    for (int nt = 0; nt < 4; nt++) {
                        float ox = acc[mt][nt][h * 2 + 0];
                        float oy = acc[mt][nt][h * 2 + 1];
                        if (is_t2) {
                            g_t2h[(size_t)gm * 32 + (coff0 >> 1) + nt * 4 + tig] = pack_h2(ox, oy);
                        } else {
                            *(float2*)(g_r2 + (size_t)gm * 64 + coff0 + nt * 8 + tig * 2)
                                = make_float2(ox, oy);
                        }
                    }
                }
            }
        }
    }
}

// ---------------- final: gather t2(half), unroll-8, out = norm( mean + b2 + r2 ) -------
__global__ void k_out(const float* __restrict__ b2, float* __restrict__ out) {
    int node = (blockIdx.x * blockDim.x + threadIdx.x) >> 5;
    int lane = threadIdx.x & 31;
    if (node >= NN) return;
    int beg = g_rowp[node], end = g_rowp[node + 1];
    float2 a0 = make_float2(0.f, 0.f);
    float2 a1 = make_float2(0.f, 0.f);
    float2 a2 = make_float2(0.f, 0.f);
    float2 a3 = make_float2(0.f, 0.f);
    int i = beg;
    for (; i + 7 < end; i += 8) {
        int idx[8];
#pragma unroll
        for (int q = 0; q < 8; q++) idx[q] = __ldg(&g_srcs[i + q]);
        unsigned u[8];
#pragma unroll
        for (int q = 0; q < 8; q++)
            u[q] = __ldg(&g_t2h[(size_t)idx[q] * 32 + lane]);
#pragma unroll
        for (int q = 0; q < 8; q += 4) {
            float2 v0 = h2f2(u[q+0]);
            float2 v1 = h2f2(u[q+1]);
            float2 v2 = h2f2(u[q+2]);
            float2 v3 = h2f2(u[q+3]);
            a0.x += v0.x; a0.y += v0.y;
            a1.x += v1.x; a1.y += v1.y;
            a2.x += v2.x; a2.y += v2.y;
            a3.x += v3.x; a3.y += v3.y;
        }
    }
    for (; i < end; i++) {
        int s0 = __ldg(&g_srcs[i]);
        float2 v0 = h2f2(__ldg(&g_t2h[(size_t)s0 * 32 + lane]));
        a0.x += v0.x; a0.y += v0.y;
    }
    float inv = 1.0f / fmaxf((float)(end - beg), 1.0f);
    float2 r  = ((const float2*)(g_r2 + (size_t)node * CC))[lane];
    float2 bb = ((const float2*)b2)[lane];
    float v0 = (a0.x + a1.x + a2.x + a3.x) * inv + bb.x + r.x;
    float v1 = (a0.y + a1.y + a2.y + a3.y) * inv + bb.y + r.y;
    float ss = v0 * v0 + v1 * v1;
#pragma unroll
    for (int o = 16; o >= 1; o >>= 1) ss += __shfl_xor_sync(0xffffffffu, ss, o);
    float sc = 1.0f / fmaxf(sqrtf(ss), 1e-12f);
    ((float2*)(out + (size_t)node * CC))[lane] = make_float2(v0 * sc, v1 * sc);
}

// ---------------- launch ----------------------------------------------------------------
extern "C" void kernel_launch(void* const* d_in, const int* in_sizes, int n_in,
                              void* d_out, int out_size) {
    const float* x    = (const float*)d_in[0];
    const int*   ei   = (const int*)  d_in[1];
    const float* W1_l = (const float*)d_in[2];
    const float* b1   = (const float*)d_in[3];
    const float* W1_r = (const float*)d_in[4];
    const float* Wl1  = (const float*)d_in[5];
    const float* bl1  = (const float*)d_in[6];
    const float* W2_l = (const float*)d_in[7];
    const float* b2   = (const float*)d_in[8];
    const float* W2_r = (const float*)d_in[9];
    float* out = (float*)d_out;

    static bool attr_done = false;
    if (!attr_done) {
        cudaFuncSetAttribute(k_fused, cudaFuncAttributeMaxDynamicSharedMemorySize, FUSED_SMEM);
        attr_done = true;
    }

    k_prep  <<<(NN * 32 + 255) / 256, 256>>>(x, W1_l, W1_r, Wl1, W2_l, W2_r);
    k_count <<<(EE / 4 + 255) / 256, 256>>>(ei);
    k_scan  <<<SCAN_NB, 256>>>();
    k_bin   <<<(EE / 4 + 255) / 256, 256>>>(ei);
    k_aggr1 <<<(NN * 32 + 255) / 256, 256>>>();
    k_fused <<<(NN + 127) / 128, 256, FUSED_SMEM>>>(b1, bl1);
    k_out   <<<(NN * 32 + 255) / 256, 256>>>(b2, out);
}

// round 15
// speedup vs baseline: 1.0747x; 1.0747x over previous
#include <cuda_runtime.h>
#include <cuda_fp16.h>
#include <math.h>

// Problem constants (fixed by the dataset)
#define NN  50000
#define EE  800000
#define FIN 128
#define HH  128
#define CC  64

#define SCAN_NB 196   // 196 * 256 = 50176 >= NN

// ---------------- device scratch (feature tensors in half2 words) -------------------
// g_icnt is zero at module load, and k_scanC re-zeroes it after use each call,
// so k_prep may count into it directly (no zeroing pass).
__device__ int      g_icnt[NN];
__device__ int      g_rowp[NN + 1];
__device__ int      g_cur [NN];
__device__ int      g_srcs[EE];
__device__ int      g_bsum[256];
__device__ int      g_boff[256];
__device__ unsigned g_xh  [NN * 64];   // x           (half2)
__device__ unsigned g_aggh[NN * 64];   // mean_aggr(x)(half2)
__device__ unsigned g_t2h [NN * 32];   // t2          (half2)
__device__ float    g_r2  [NN * CC];   // h2 @ W2_r^T (f32)
__device__ unsigned g_wh0[128 * 128];  // [W1_l|W1_r] rows of 256 halfs
__device__ unsigned g_wh1[128 * 128];  // Wl1         rows of 256 halfs
__device__ unsigned g_wh2[128 * 64];   // [W2_l;W2_r] rows of 128 halfs

__device__ __forceinline__ unsigned pack_h2(float lo, float hi) {
    __half2 h = __floats2half2_rn(lo, hi);
    return *(unsigned*)&h;
}
__device__ __forceinline__ float2 h2f2(unsigned u) {
    return __half22float2(*(__half2*)&u);
}

// ---------------- prep: x->fp16, weights->fp16, degree count (fused) -------------------
__global__ void k_prep(const float* __restrict__ x, const int* __restrict__ ei,
                       const float* __restrict__ W1_l, const float* __restrict__ W1_r,
                       const float* __restrict__ Wl1,
                       const float* __restrict__ W2_l, const float* __restrict__ W2_r) {
    int i = blockIdx.x * blockDim.x + threadIdx.x;   // uint2 unit = 4 floats
    if (i < NN * 32) {
        float4 v = ((const float4*)x)[i];
        ((uint2*)g_xh)[i] = make_uint2(pack_h2(v.x, v.y), pack_h2(v.z, v.w));
    }
    if (i < EE / 4) {   // degree count, 4 edges/thread (g_icnt pre-zeroed invariant)
        int4 d = *(const int4*)(ei + EE + i * 4);
        atomicAdd(&g_icnt[d.x], 1);
        atomicAdd(&g_icnt[d.y], 1);
        atomicAdd(&g_icnt[d.z], 1);
        atomicAdd(&g_icnt[d.w], 1);
    }
    if (i < 128 * 128) {
        int j = i >> 7, k = (i & 127) * 2;
        float a = (k < 128) ? W1_l[j * 128 + k]     : W1_r[j * 128 + k - 128];
        float b = (k < 128) ? W1_l[j * 128 + k + 1] : W1_r[j * 128 + k + 1 - 128];
        g_wh0[i] = pack_h2(a, b);
        g_wh1[i] = pack_h2(Wl1[j * 256 + k], Wl1[j * 256 + k + 1]);
    }
    if (i < 128 * 64) {
        int j = i >> 6, k = (i & 63) * 2;
        float a = (j < 64) ? W2_l[j * 128 + k]     : W2_r[(j - 64) * 128 + k];
        float b = (j < 64) ? W2_l[j * 128 + k + 1] : W2_r[(j - 64) * 128 + k + 1];
        g_wh2[i] = pack_h2(a, b);
    }
}

// ---------------- parallel 3-phase exclusive scan ---------------------------------------
__global__ void k_scanA() {
    __shared__ int sm[256];
    int t = threadIdx.x;
    int i = blockIdx.x * 256 + t;
    sm[t] = (i < NN) ? g_icnt[i] : 0;
    __syncthreads();
#pragma unroll
    for (int o = 128; o > 0; o >>= 1) {
        if (t < o) sm[t] += sm[t + o];
        __syncthreads();
    }
    if (t == 0) g_bsum[blockIdx.x] = sm[0];
}

__global__ void k_scanB() {
    __shared__ int sm[256];
    int t = threadIdx.x;
    int v = (t < SCAN_NB) ? g_bsum[t] : 0;
    sm[t] = v;
    __syncthreads();
#pragma unroll
    for (int o = 1; o < 256; o <<= 1) {
        int u = (t >= o) ? sm[t - o] : 0;
        __syncthreads();
        sm[t] += u;
        __syncthreads();
    }
    g_boff[t] = sm[t] - v;   // exclusive block offset
}

__global__ void k_scanC() {
    __shared__ int sm[256];
    int t = threadIdx.x;
    int i = blockIdx.x * 256 + t;
    int v = (i < NN) ? g_icnt[i] : 0;
    if (i < NN) g_icnt[i] = 0;     // reset for next graph replay (invariant)
    sm[t] = v;
    __syncthreads();
#pragma unroll
    for (int o = 1; o < 256; o <<= 1) {
        int u = (t >= o) ? sm[t - o] : 0;
        __syncthreads();
        sm[t] += u;
        __syncthreads();
    }
    int ex = sm[t] - v + g_boff[blockIdx.x];
    if (i < NN) { g_rowp[i] = ex; g_cur[i] = ex; }
    if (i == NN) g_rowp[NN] = ex;   // == EE
}

// ---------------- bin: srcs sorted by dst (4 edges/thread) -----------------------------
__global__ void k_bin(const int* __restrict__ ei) {
    int e0 = (blockIdx.x * blockDim.x + threadIdx.x) * 4;
    if (e0 >= EE) return;
    int4 s = *(const int4*)(ei + e0);
    int4 d = *(const int4*)(ei + EE + e0);
    int p0 = atomicAdd(&g_cur[d.x], 1);
    int p1 = atomicAdd(&g_cur[d.y], 1);
    int p2 = atomicAdd(&g_cur[d.z], 1);
    int p3 = atomicAdd(&g_cur[d.w], 1);
    g_srcs[p0] = s.x; g_srcs[p1] = s.y; g_srcs[p2] = s.z; g_srcs[p3] = s.w;
}

// ---------------- layer-1 mean aggregation: warp/node, unroll-8 ------------------------
__global__ void k_aggr1() {
    int node = (blockIdx.x * blockDim.x + threadIdx.x) >> 5;
    int lane = threadIdx.x & 31;
    if (node >= NN) return;
    int beg = g_rowp[node], end = g_rowp[node + 1];
    float4 a0 = make_float4(0.f, 0.f, 0.f, 0.f);
    float4 a1 = make_float4(0.f, 0.f, 0.f, 0.f);
    float4 a2 = make_float4(0.f, 0.f, 0.f, 0.f);
    float4 a3 = make_float4(0.f, 0.f, 0.f, 0.f);
    int i = beg;
    for (; i + 7 < end; i += 8) {
        int idx[8];
#pragma unroll
        for (int q = 0; q < 8; q++) idx[q] = __ldg(&g_srcs[i + q]);
        uint2 u[8];
#pragma unroll
        for (int q = 0; q < 8; q++)
            u[q] = *(const uint2*)(g_xh + (size_t)idx[q] * 64 + lane * 2);
#pragma unroll
        for (int q = 0; q < 8; q += 4) {
            float2 p0 = h2f2(u[q+0].x), p1 = h2f2(u[q+0].y);
            float2 q0 = h2f2(u[q+1].x), q1 = h2f2(u[q+1].y);
            float2 r0 = h2f2(u[q+2].x), r1 = h2f2(u[q+2].y);
            float2 t0 = h2f2(u[q+3].x), t1 = h2f2(u[q+3].y);
            a0.x += p0.x; a0.y += p0.y; a0.z += p1.x; a0.w += p1.y;
            a1.x += q0.x; a1.y += q0.y; a1.z += q1.x; a1.w += q1.y;
            a2.x += r0.x; a2.y += r0.y; a2.z += r1.x; a2.w += r1.y;
            a3.x += t0.x; a3.y += t0.y; a3.z += t1.x; a3.w += t1.y;
        }
    }
    for (; i < end; i++) {
        int s0 = __ldg(&g_srcs[i]);
        uint2 u0 = *(const uint2*)(g_xh + (size_t)s0 * 64 + lane * 2);
        float2 p0 = h2f2(u0.x), p1 = h2f2(u0.y);
        a0.x += p0.x; a0.y += p0.y; a0.z += p1.x; a0.w += p1.y;
    }
    float inv = 1.0f / fmaxf((float)(end - beg), 1.0f);
    uint2 o;
    o.x = pack_h2((a0.x + a1.x + a2.x + a3.x) * inv, (a0.y + a1.y + a2.y + a3.y) * inv);
    o.y = pack_h2((a0.z + a1.z + a2.z + a3.z) * inv, (a0.w + a1.w + a2.w + a3.w) * inv);
    *(uint2*)(g_aggh + (size_t)node * 64 + lane * 2) = o;
}

// ---------------- fp16 MMA helper ------------------------------------------------------
#define MMA_F16(d, a, b)                                                          \
    asm volatile("mma.sync.aligned.m16n8k16.row.col.f32.f16.f16.f32 "             \
                 "{%0,%1,%2,%3}, {%4,%5,%6,%7}, {%8,%9}, {%0,%1,%2,%3};"          \
                 : "+f"(d[0]), "+f"(d[1]), "+f"(d[2]), "+f"(d[3])                 \
                 : "r"(a[0]), "r"(a[1]), "r"(a[2]), "r"(a[3]),                    \
                   "r"(b[0]), "r"(b[1]))

// ---------------- FUSED 3-GEMM kernel (proven R11 structure) ----------------------------
// Per CTA: 128 nodes. A operand lives in smem for the whole kernel:
//   XA words 0..63  = agg (later h, then h2), 64..127 = x (resident)
// GEMM0: [agg|x]@wh0^T -> +b1, L2-norm, relu -> h   -> XA[0..63]
// GEMM1: [x|h] @wh1^T -> +bl1, relu          -> h2  -> XA[0..63]
// GEMM2: h2    @wh2^T -> t2 (half) + r2 (f32)
#define RSX 132   // XA row stride in half2 words (132 % 32 == 4 -> conflict-free)
#define RSW 36    // Ws row stride in half2 words
#define FUSED_SMEM ((128 * RSX + 128 * RSW) * 4 + 512 * 4 + 256 * 4)

__global__ __launch_bounds__(256)
void k_fused(const float* __restrict__ b1, const float* __restrict__ bl1) {
    extern __shared__ unsigned smem[];
    unsigned* XA  = smem;                       // 128*132 words
    unsigned* Ws  = smem + 128 * RSX;           // 128*36 words
    float*    rss = (float*)(Ws + 128 * RSW);   // 512 floats
    float*    bsm = rss + 512;                  // 256 floats: b1 | bl1

    const int tid  = threadIdx.x;
    const int lane = tid & 31;
    const int w    = tid >> 5;
    const int wm   = w & 1;        // 0..1 (64 rows each)
    const int wn   = w >> 1;       // 0..3 (32 cols each)
    const int qid  = lane >> 2;    // 0..7
    const int tig  = lane & 3;     // 0..3
    const int m0   = blockIdx.x * 128;

    bsm[tid] = (tid < 128) ? b1[tid] : bl1[tid - 128];

    // ---- fill XA: words 0..63 = agg, 64..127 = x ----
#pragma unroll
    for (int p = 0; p < 16; p++) {
        int f    = tid + p * 256;        // 0..4095
        int row  = f >> 5;               // 0..127
        int word = (f & 31) * 4;         // uint4-aligned word 0..124
        int gm   = min(m0 + row, NN - 1);
        uint4 v = (word < 64)
            ? *(const uint4*)(g_aggh + (size_t)gm * 64 + word)
            : *(const uint4*)(g_xh   + (size_t)gm * 64 + (word - 64));
        *(uint4*)(&XA[row * RSX + word]) = v;
    }

    // ---- weight chunk streaming ----
    uint4 rw4[4];
    auto loadW = [&](int idx) {   // flat chunk idx 0..9
        const unsigned* base; int WR, off;
        if (idx < 4)      { base = g_wh0; WR = 128; off = idx * 32; }
        else if (idx < 8) { base = g_wh1; WR = 128; off = (idx - 4) * 32; }
        else              { base = g_wh2; WR = 64;  off = (idx - 8) * 32; }
#pragma unroll
        for (int p = 0; p < 4; p++) {
            int f = tid + p * 256;
            int j = f >> 3, seg = f & 7;
            rw4[p] = *(const uint4*)(base + j * WR + off + seg * 4);
        }
    };
    auto storeW = [&]() {
#pragma unroll
        for (int p = 0; p < 4; p++) {
            int f = tid + p * 256;
            int j = f >> 3, seg = f & 7;
            *(uint4*)(&Ws[j * RSW + seg * 4]) = rw4[p];
        }
    };

    float acc[4][4][4];
    auto resetAcc = [&]() {
#pragma unroll
        for (int mt = 0; mt < 4; mt++)
#pragma unroll
            for (int nt = 0; nt < 4; nt++)
#pragma unroll
                for (int c = 0; c < 4; c++) acc[mt][nt][c] = 0.f;
    };

    int widx = 0;
    loadW(0); widx = 1;

    auto runChunks = [&](int nch, int gsel) {
        for (int c = 0; c < nch; c++) {
            __syncthreads();
            storeW();
            __syncthreads();
            if (widx < 10) { loadW(widx); widx++; }
            int offA = (gsel == 1) ? ((c < 2) ? 64 + c * 32 : (c - 2) * 32)
                                   : c * 32;
#pragma unroll
            for (int ks = 0; ks < 4; ks++) {
                const int kb = ks * 8;
                unsigned a[4][4];
#pragma unroll
                for (int mt = 0; mt < 4; mt++) {
                    int r0 = wm * 64 + mt * 16 + qid;
                    a[mt][0] = XA[r0 * RSX + offA + kb + tig];
                    a[mt][1] = XA[(r0 + 8) * RSX + offA + kb + tig];
                    a[mt][2] = XA[r0 * RSX + offA + kb + tig + 4];
                    a[mt][3] = XA[(r0 + 8) * RSX + offA + kb + tig + 4];
                }
                unsigned b[4][2];
#pragma unroll
                for (int nt = 0; nt < 4; nt++) {
                    int c0 = wn * 32 + nt * 8 + qid;
                    b[nt][0] = Ws[c0 * RSW + kb + tig];
                    b[nt][1] = Ws[c0 * RSW + kb + tig + 4];
                }
#pragma unroll
                for (int mt = 0; mt < 4; mt++)
#pragma unroll
                    for (int nt = 0; nt < 4; nt++)
                        MMA_F16(acc[mt][nt], a[mt], b[nt]);
            }
        }
    };

    // ================= GEMM0: [agg|x] @ wh0^T =================
    resetAcc();
    runChunks(4, 0);

    // epilogue0: +b1, L2 row-norm, relu, h -> XA words 0..63
    {
#pragma unroll
        for (int nt = 0; nt < 4; nt++) {
            float bx = bsm[wn * 32 + nt * 8 + tig * 2];
            float by = bsm[wn * 32 + nt * 8 + tig * 2 + 1];
#pragma unroll
            for (int mt = 0; mt < 4; mt++) {
                acc[mt][nt][0] += bx; acc[mt][nt][1] += by;
                acc[mt][nt][2] += bx; acc[mt][nt][3] += by;
            }
        }
        float ssl[4][2];
#pragma unroll
        for (int mt = 0; mt < 4; mt++) {
            float s0 = 0.f, s1 = 0.f;
#pragma unroll
            for (int nt = 0; nt < 4; nt++) {
                s0 += acc[mt][nt][0] * acc[mt][nt][0] + acc[mt][nt][1] * acc[mt][nt][1];
                s1 += acc[mt][nt][2] * acc[mt][nt][2] + acc[mt][nt][3] * acc[mt][nt][3];
            }
            s0 += __shfl_xor_sync(0xffffffffu, s0, 1);
            s0 += __shfl_xor_sync(0xffffffffu, s0, 2);
            s1 += __shfl_xor_sync(0xffffffffu, s1, 1);
            s1 += __shfl_xor_sync(0xffffffffu, s1, 2);
            ssl[mt][0] = s0; ssl[mt][1] = s1;
        }
        if (tig == 0) {
#pragma unroll
            for (int mt = 0; mt < 4; mt++) {
                int r0 = wm * 64 + mt * 16 + qid;
                rss[(r0)     * 4 + wn] = ssl[mt][0];
                rss[(r0 + 8) * 4 + wn] = ssl[mt][1];
            }
        }
        __syncthreads();   // all GEMM0 MMAs done before XA[0..63] overwrite
#pragma unroll
        for (int mt = 0; mt < 4; mt++) {
#pragma unroll
            for (int h = 0; h < 2; h++) {
                int r = wm * 64 + mt * 16 + qid + h * 8;
                float ss = rss[r * 4 + 0] + rss[r * 4 + 1] + rss[r * 4 + 2] + rss[r * 4 + 3];
                float scl = 1.0f / fmaxf(sqrtf(ss), 1e-12f);
#pragma unroll
                for (int nt = 0; nt < 4; nt++) {
                    float ox = fmaxf(acc[mt][nt][h * 2 + 0] * scl, 0.f);
                    float oy = fmaxf(acc[mt][nt][h * 2 + 1] * scl, 0.f);
                    XA[r * RSX + wn * 16 + nt * 4 + tig] = pack_h2(ox, oy);
                }
            }
        }
    }

    // ================= GEMM1: [x|h] @ wh1^T =================
    resetAcc();
    runChunks(4, 1);

    // epilogue1: +bl1, relu, h2 -> XA words 0..63
    __syncthreads();   // all GEMM1 MMAs done before overwriting h
    {
#pragma unroll
        for (int mt = 0; mt < 4; mt++) {
#pragma unroll
            for (int h = 0; h < 2; h++) {
                int r = wm * 64 + mt * 16 + qid + h * 8;
#pragma unroll
                for (int nt = 0; nt < 4; nt++) {
                    float bx = bsm[128 + wn * 32 + nt * 8 + tig * 2];
                    float by = bsm[128 + wn * 32 + nt * 8 + tig * 2 + 1];
                    float ox = fmaxf(acc[mt][nt][h * 2 + 0] + bx, 0.f);
                    float oy = fmaxf(acc[mt][nt][h * 2 + 1] + by, 0.f);
                    XA[r * RSX + wn * 16 + nt * 4 + tig] = pack_h2(ox, oy);
                }
            }
        }
    }

    // ================= GEMM2: h2 @ wh2^T =================
    resetAcc();
    runChunks(2, 2);

    // epilogue2: cols 0..63 -> t2 (half2), 64..127 -> r2 (f32)
    {
        const bool is_t2 = (wn < 2);
        const int coff0 = is_t2 ? wn * 32 : (wn - 2) * 32;
#pragma unroll
        for (int mt = 0; mt < 4; mt++) {
#pragma unroll
            for (int h = 0; h < 2; h++) {
                int gm = m0 + wm * 64 + mt * 16 + qid + h * 8;
                if (gm < NN) {
#pragma unroll
                    for (int nt = 0; nt < 4; nt++) {
                        float ox = acc[mt][nt][h * 2 + 0];
                        float oy = acc[mt][nt][h * 2 + 1];
                        if (is_t2) {
                            g_t2h[(size_t)gm * 32 + (coff0 >> 1) + nt * 4 + tig] = pack_h2(ox, oy);
                        } else {
                            *(float2*)(g_r2 + (size_t)gm * 64 + coff0 + nt * 8 + tig * 2)
                                = make_float2(ox, oy);
                        }
                    }
                }
            }
        }
    }
}

// ---------------- final: gather t2(half), unroll-8, out = norm( mean + b2 + r2 ) -------
__global__ void k_out(const float* __restrict__ b2, float* __restrict__ out) {
    int node = (blockIdx.x * blockDim.x + threadIdx.x) >> 5;
    int lane = threadIdx.x & 31;
    if (node >= NN) return;
    int beg = g_rowp[node], end = g_rowp[node + 1];
    float2 a0 = make_float2(0.f, 0.f);
    float2 a1 = make_float2(0.f, 0.f);
    float2 a2 = make_float2(0.f, 0.f);
    float2 a3 = make_float2(0.f, 0.f);
    int i = beg;
    for (; i + 7 < end; i += 8) {
        int idx[8];
#pragma unroll
        for (int q = 0; q < 8; q++) idx[q] = __ldg(&g_srcs[i + q]);
        unsigned u[8];
#pragma unroll
        for (int q = 0; q < 8; q++)
            u[q] = __ldg(&g_t2h[(size_t)idx[q] * 32 + lane]);
#pragma unroll
        for (int q = 0; q < 8; q += 4) {
            float2 v0 = h2f2(u[q+0]);
            float2 v1 = h2f2(u[q+1]);
            float2 v2 = h2f2(u[q+2]);
            float2 v3 = h2f2(u[q+3]);
            a0.x += v0.x; a0.y += v0.y;
            a1.x += v1.x; a1.y += v1.y;
            a2.x += v2.x; a2.y += v2.y;
            a3.x += v3.x; a3.y += v3.y;
        }
    }
    for (; i < end; i++) {
        int s0 = __ldg(&g_srcs[i]);
        float2 v0 = h2f2(__ldg(&g_t2h[(size_t)s0 * 32 + lane]));
        a0.x += v0.x; a0.y += v0.y;
    }
    float inv = 1.0f / fmaxf((float)(end - beg), 1.0f);
    float2 r  = ((const float2*)(g_r2 + (size_t)node * CC))[lane];
    float2 bb = ((const float2*)b2)[lane];
    float v0 = (a0.x + a1.x + a2.x + a3.x) * inv + bb.x + r.x;
    float v1 = (a0.y + a1.y + a2.y + a3.y) * inv + bb.y + r.y;
    float ss = v0 * v0 + v1 * v1;
#pragma unroll
    for (int o = 16; o >= 1; o >>= 1) ss += __shfl_xor_sync(0xffffffffu, ss, o);
    float sc = 1.0f / fmaxf(sqrtf(ss), 1e-12f);
    ((float2*)(out + (size_t)node * CC))[lane] = make_float2(v0 * sc, v1 * sc);
}

// ---------------- launch ----------------------------------------------------------------
extern "C" void kernel_launch(void* const* d_in, const int* in_sizes, int n_in,
                              void* d_out, int out_size) {
    const float* x    = (const float*)d_in[0];
    const int*   ei   = (const int*)  d_in[1];
    const float* W1_l = (const float*)d_in[2];
    const float* b1   = (const float*)d_in[3];
    const float* W1_r = (const float*)d_in[4];
    const float* Wl1  = (const float*)d_in[5];
    const float* bl1  = (const float*)d_in[6];
    const float* W2_l = (const float*)d_in[7];
    const float* b2   = (const float*)d_in[8];
    const float* W2_r = (const float*)d_in[9];
    float* out = (float*)d_out;

    static bool attr_done = false;
    if (!attr_done) {
        cudaFuncSetAttribute(k_fused, cudaFuncAttributeMaxDynamicSharedMemorySize, FUSED_SMEM);
        attr_done = true;
    }

    k_prep  <<<(NN * 32 + 255) / 256, 256>>>(x, ei, W1_l, W1_r, Wl1, W2_l, W2_r);
    k_scanA <<<SCAN_NB, 256>>>();
    k_scanB <<<1, 256>>>();
    k_scanC <<<SCAN_NB, 256>>>();
    k_bin   <<<(EE / 4 + 255) / 256, 256>>>(ei);
    k_aggr1 <<<(NN * 32 + 255) / 256, 256>>>();
    k_fused <<<(NN + 127) / 128, 256, FUSED_SMEM>>>(b1, bl1);
    k_out   <<<(NN * 32 + 255) / 256, 256>>>(b2, out);
}

// round 16
// speedup vs baseline: 1.0961x; 1.0199x over previous
#include <cuda_runtime.h>
#include <cuda_fp16.h>
#include <math.h>

// Problem constants (fixed by the dataset)
#define NN  50000
#define EE  800000
#define FIN 128
#define HH  128
#define CC  64

#define SCAN_NB 196   // 196 * 256 = 50176 >= NN

// ---------------- device scratch (feature tensors in half2 words) -------------------
// g_icnt is zero at module load, and k_scanC re-zeroes it after use each call,
// so k_prep may count into it directly (no zeroing pass).
__device__ int      g_icnt[NN];
__device__ int      g_rowp[NN + 1];
__device__ int      g_cur [NN];
__device__ int      g_srcs[EE];
__device__ int      g_bsum[256];
__device__ unsigned g_xh  [NN * 64];   // x           (half2)
__device__ unsigned g_aggh[NN * 64];   // mean_aggr(x)(half2)
__device__ unsigned g_t2h [NN * 32];   // t2          (half2)
__device__ float    g_r2  [NN * CC];   // h2 @ W2_r^T (f32)
__device__ unsigned g_wh0[128 * 128];  // [W1_l|W1_r] rows of 256 halfs
__device__ unsigned g_wh1[128 * 128];  // Wl1         rows of 256 halfs
__device__ unsigned g_wh2[128 * 64];   // [W2_l;W2_r] rows of 128 halfs

__device__ __forceinline__ unsigned pack_h2(float lo, float hi) {
    __half2 h = __floats2half2_rn(lo, hi);
    return *(unsigned*)&h;
}
__device__ __forceinline__ float2 h2f2(unsigned u) {
    return __half22float2(*(__half2*)&u);
}

// ---------------- prep: x->fp16, weights->fp16, degree count (fused) -------------------
__global__ void k_prep(const float* __restrict__ x, const int* __restrict__ ei,
                       const float* __restrict__ W1_l, const float* __restrict__ W1_r,
                       const float* __restrict__ Wl1,
                       const float* __restrict__ W2_l, const float* __restrict__ W2_r) {
    int i = blockIdx.x * blockDim.x + threadIdx.x;   // uint2 unit = 4 floats
    if (i < NN * 32) {
        float4 v = ((const float4*)x)[i];
        ((uint2*)g_xh)[i] = make_uint2(pack_h2(v.x, v.y), pack_h2(v.z, v.w));
    }
    if (i < EE / 4) {   // degree count, 4 edges/thread (g_icnt pre-zeroed invariant)
        int4 d = *(const int4*)(ei + EE + i * 4);
        atomicAdd(&g_icnt[d.x], 1);
        atomicAdd(&g_icnt[d.y], 1);
        atomicAdd(&g_icnt[d.z], 1);
        atomicAdd(&g_icnt[d.w], 1);
    }
    if (i < 128 * 128) {
        int j = i >> 7, k = (i & 127) * 2;
        float a = (k < 128) ? W1_l[j * 128 + k]     : W1_r[j * 128 + k - 128];
        float b = (k < 128) ? W1_l[j * 128 + k + 1] : W1_r[j * 128 + k + 1 - 128];
        g_wh0[i] = pack_h2(a, b);
        g_wh1[i] = pack_h2(Wl1[j * 256 + k], Wl1[j * 256 + k + 1]);
    }
    if (i < 128 * 64) {
        int j = i >> 6, k = (i & 63) * 2;
        float a = (j < 64) ? W2_l[j * 128 + k]     : W2_r[(j - 64) * 128 + k];
        float b = (j < 64) ? W2_l[j * 128 + k + 1] : W2_r[(j - 64) * 128 + k + 1];
        g_wh2[i] = pack_h2(a, b);
    }
}

// ---------------- 2-phase scan: block sums, then per-block offset + local scan ---------
__global__ void k_scanA() {
    __shared__ int sm[256];
    int t = threadIdx.x;
    int i = blockIdx.x * 256 + t;
    sm[t] = (i < NN) ? g_icnt[i] : 0;
    __syncthreads();
#pragma unroll
    for (int o = 128; o > 0; o >>= 1) {
        if (t < o) sm[t] += sm[t + o];
        __syncthreads();
    }
    if (t == 0) g_bsum[blockIdx.x] = sm[0];
}

__global__ void k_scanC() {
    __shared__ int sm[256];
    __shared__ int rb[256];
    const int t = threadIdx.x;
    const int b = blockIdx.x;
    const int i = b * 256 + t;

    // block-exclusive offset: sum of g_bsum[0..b-1] (reduced locally, no scanB kernel)
    rb[t] = (t < b && t < SCAN_NB) ? g_bsum[t] : 0;
    // local element scan input
    int v = (i < NN) ? g_icnt[i] : 0;
    if (i < NN) g_icnt[i] = 0;     // reset for next graph replay (invariant)
    sm[t] = v;
    __syncthreads();
#pragma unroll
    for (int o = 128; o > 0; o >>= 1) {
        if (t < o) rb[t] += rb[t + o];
        __syncthreads();
    }
    const int base = rb[0];
    __syncthreads();   // rb reads done before any reuse; sm scan below
#pragma unroll
    for (int o = 1; o < 256; o <<= 1) {
        int u = (t >= o) ? sm[t - o] : 0;
        __syncthreads();
        sm[t] += u;
        __syncthreads();
    }
    int ex = sm[t] - v + base;
    if (i < NN) { g_rowp[i] = ex; g_cur[i] = ex; }
    if (i == NN) g_rowp[NN] = ex;   // == EE
}

// ---------------- bin: srcs sorted by dst (4 edges/thread) -----------------------------
__global__ void k_bin(const int* __restrict__ ei) {
    int e0 = (blockIdx.x * blockDim.x + threadIdx.x) * 4;
    if (e0 >= EE) return;
    int4 s = *(const int4*)(ei + e0);
    int4 d = *(const int4*)(ei + EE + e0);
    int p0 = atomicAdd(&g_cur[d.x], 1);
    int p1 = atomicAdd(&g_cur[d.y], 1);
    int p2 = atomicAdd(&g_cur[d.z], 1);
    int p3 = atomicAdd(&g_cur[d.w], 1);
    g_srcs[p0] = s.x; g_srcs[p1] = s.y; g_srcs[p2] = s.z; g_srcs[p3] = s.w;
}

// ---------------- layer-1 mean aggregation: warp/node, unroll-8 ------------------------
__global__ void k_aggr1() {
    int node = (blockIdx.x * blockDim.x + threadIdx.x) >> 5;
    int lane = threadIdx.x & 31;
    if (node >= NN) return;
    int beg = g_rowp[node], end = g_rowp[node + 1];
    float4 a0 = make_float4(0.f, 0.f, 0.f, 0.f);
    float4 a1 = make_float4(0.f, 0.f, 0.f, 0.f);
    float4 a2 = make_float4(0.f, 0.f, 0.f, 0.f);
    float4 a3 = make_float4(0.f, 0.f, 0.f, 0.f);
    int i = beg;
    for (; i + 7 < end; i += 8) {
        int idx[8];
#pragma unroll
        for (int q = 0; q < 8; q++) idx[q] = __ldg(&g_srcs[i + q]);
        uint2 u[8];
#pragma unroll
        for (int q = 0; q < 8; q++)
            u[q] = *(const uint2*)(g_xh + (size_t)idx[q] * 64 + lane * 2);
#pragma unroll
        for (int q = 0; q < 8; q += 4) {
            float2 p0 = h2f2(u[q+0].x), p1 = h2f2(u[q+0].y);
            float2 q0 = h2f2(u[q+1].x), q1 = h2f2(u[q+1].y);
            float2 r0 = h2f2(u[q+2].x), r1 = h2f2(u[q+2].y);
            float2 t0 = h2f2(u[q+3].x), t1 = h2f2(u[q+3].y);
            a0.x += p0.x; a0.y += p0.y; a0.z += p1.x; a0.w += p1.y;
            a1.x += q0.x; a1.y += q0.y; a1.z += q1.x; a1.w += q1.y;
            a2.x += r0.x; a2.y += r0.y; a2.z += r1.x; a2.w += r1.y;
            a3.x += t0.x; a3.y += t0.y; a3.z += t1.x; a3.w += t1.y;
        }
    }
    for (; i < end; i++) {
        int s0 = __ldg(&g_srcs[i]);
        uint2 u0 = *(const uint2*)(g_xh + (size_t)s0 * 64 + lane * 2);
        float2 p0 = h2f2(u0.x), p1 = h2f2(u0.y);
        a0.x += p0.x; a0.y += p0.y; a0.z += p1.x; a0.w += p1.y;
    }
    float inv = 1.0f / fmaxf((float)(end - beg), 1.0f);
    uint2 o;
    o.x = pack_h2((a0.x + a1.x + a2.x + a3.x) * inv, (a0.y + a1.y + a2.y + a3.y) * inv);
    o.y = pack_h2((a0.z + a1.z + a2.z + a3.z) * inv, (a0.w + a1.w + a2.w + a3.w) * inv);
    *(uint2*)(g_aggh + (size_t)node * 64 + lane * 2) = o;
}

// ---------------- fp16 MMA helper ------------------------------------------------------
#define MMA_F16(d, a, b)                                                          \
    asm volatile("mma.sync.aligned.m16n8k16.row.col.f32.f16.f16.f32 "             \
                 "{%0,%1,%2,%3}, {%4,%5,%6,%7}, {%8,%9}, {%0,%1,%2,%3};"          \
                 : "+f"(d[0]), "+f"(d[1]), "+f"(d[2]), "+f"(d[3])                 \
                 : "r"(a[0]), "r"(a[1]), "r"(a[2]), "r"(a[3]),                    \
                   "r"(b[0]), "r"(b[1]))

// ---------------- FUSED 3-GEMM kernel (proven R11 structure) ----------------------------
// Per CTA: 128 nodes. A operand lives in smem for the whole kernel:
//   XA words 0..63  = agg (later h, then h2), 64..127 = x (resident)
// GEMM0: [agg|x]@wh0^T -> +b1, L2-norm, relu -> h   -> XA[0..63]
// GEMM1: [x|h] @wh1^T -> +bl1, relu          -> h2  -> XA[0..63]
// GEMM2: h2    @wh2^T -> t2 (half) + r2 (f32)
#define RSX 132   // XA row stride in half2 words (132 % 32 == 4 -> conflict-free)
#define RSW 36    // Ws row stride in half2 words
#define FUSED_SMEM ((128 * RSX + 128 * RSW) * 4 + 512 * 4 + 256 * 4)

__global__ __launch_bounds__(256)
void k_fused(const float* __restrict__ b1, const float* __restrict__ bl1) {
    extern __shared__ unsigned smem[];
    unsigned* XA  = smem;                       // 128*132 words
    unsigned* Ws  = smem + 128 * RSX;           // 128*36 words
    float*    rss = (float*)(Ws + 128 * RSW);   // 512 floats
    float*    bsm = rss + 512;                  // 256 floats: b1 | bl1

    const int tid  = threadIdx.x;
    const int lane = tid & 31;
    const int w    = tid >> 5;
    const int wm   = w & 1;        // 0..1 (64 rows each)
    const int wn   = w >> 1;       // 0..3 (32 cols each)
    const int qid  = lane >> 2;    // 0..7
    const int tig  = lane & 3;     // 0..3
    const int m0   = blockIdx.x * 128;

    bsm[tid] = (tid < 128) ? b1[tid] : bl1[tid - 128];

    // ---- fill XA: words 0..63 = agg, 64..127 = x ----
#pragma unroll
    for (int p = 0; p < 16; p++) {
        int f    = tid + p * 256;        // 0..4095
        int row  = f >> 5;               // 0..127
        int word = (f & 31) * 4;         // uint4-aligned word 0..124
        int gm   = min(m0 + row, NN - 1);
        uint4 v = (word < 64)
            ? *(const uint4*)(g_aggh + (size_t)gm * 64 + word)
            : *(const uint4*)(g_xh   + (size_t)gm * 64 + (word - 64));
        *(uint4*)(&XA[row * RSX + word]) = v;
    }

    // ---- weight chunk streaming ----
    uint4 rw4[4];
    auto loadW = [&](int idx) {   // flat chunk idx 0..9
        const unsigned* base; int WR, off;
        if (idx < 4)      { base = g_wh0; WR = 128; off = idx * 32; }
        else if (idx < 8) { base = g_wh1; WR = 128; off = (idx - 4) * 32; }
        else              { base = g_wh2; WR = 64;  off = (idx - 8) * 32; }
#pragma unroll
        for (int p = 0; p < 4; p++) {
            int f = tid + p * 256;
            int j = f >> 3, seg = f & 7;
            rw4[p] = *(const uint4*)(base + j * WR + off + seg * 4);
        }
    };
    auto storeW = [&]() {
#pragma unroll
        for (int p = 0; p < 4; p++) {
            int f = tid + p * 256;
            int j = f >> 3, seg = f & 7;
            *(uint4*)(&Ws[j * RSW + seg * 4]) = rw4[p];
        }
    };

    float acc[4][4][4];
    auto resetAcc = [&]() {
#pragma unroll
        for (int mt = 0; mt < 4; mt++)
#pragma unroll
            for (int nt = 0; nt < 4; nt++)
#pragma unroll
                for (int c = 0; c < 4; c++) acc[mt][nt][c] = 0.f;
    };

    int widx = 0;
    loadW(0); widx = 1;

    auto runChunks = [&](int nch, int gsel) {
        for (int c = 0; c < nch; c++) {
            __syncthreads();
            storeW();
            __syncthreads();
            if (widx < 10) { loadW(widx); widx++; }
            int offA = (gsel == 1) ? ((c < 2) ? 64 + c * 32 : (c - 2) * 32)
                                   : c * 32;
#pragma unroll
            for (int ks = 0; ks < 4; ks++) {
                const int kb = ks * 8;
                unsigned a[4][4];
#pragma unroll
                for (int mt = 0; mt < 4; mt++) {
                    int r0 = wm * 64 + mt * 16 + qid;
                    a[mt][0] = XA[r0 * RSX + offA + kb + tig];
                    a[mt][1] = XA[(r0 + 8) * RSX + offA + kb + tig];
                    a[mt][2] = XA[r0 * RSX + offA + kb + tig + 4];
                    a[mt][3] = XA[(r0 + 8) * RSX + offA + kb + tig + 4];
                }
                unsigned b[4][2];
#pragma unroll
                for (int nt = 0; nt < 4; nt++) {
                    int c0 = wn * 32 + nt * 8 + qid;
                    b[nt][0] = Ws[c0 * RSW + kb + tig];
                    b[nt][1] = Ws[c0 * RSW + kb + tig + 4];
                }
#pragma unroll
                for (int mt = 0; mt < 4; mt++)
#pragma unroll
                    for (int nt = 0; nt < 4; nt++)
                        MMA_F16(acc[mt][nt], a[mt], b[nt]);
            }
        }
    };

    // ================= GEMM0: [agg|x] @ wh0^T =================
    resetAcc();
    runChunks(4, 0);

    // epilogue0: +b1, L2 row-norm, relu, h -> XA words 0..63
    {
#pragma unroll
        for (int nt = 0; nt < 4; nt++) {
            float bx = bsm[wn * 32 + nt * 8 + tig * 2];
            float by = bsm[wn * 32 + nt * 8 + tig * 2 + 1];
#pragma unroll
            for (int mt = 0; mt < 4; mt++) {
                acc[mt][nt][0] += bx; acc[mt][nt][1] += by;
                acc[mt][nt][2] += bx; acc[mt][nt][3] += by;
            }
        }
        float ssl[4][2];
#pragma unroll
        for (int mt = 0; mt < 4; mt++) {
            float s0 = 0.f, s1 = 0.f;
#pragma unroll
            for (int nt = 0; nt < 4; nt++) {
                s0 += acc[mt][nt][0] * acc[mt][nt][0] + acc[mt][nt][1] * acc[mt][nt][1];
                s1 += acc[mt][nt][2] * acc[mt][nt][2] + acc[mt][nt][3] * acc[mt][nt][3];
            }
            s0 += __shfl_xor_sync(0xffffffffu, s0, 1);
            s0 += __shfl_xor_sync(0xffffffffu, s0, 2);
            s1 += __shfl_xor_sync(0xffffffffu, s1, 1);
            s1 += __shfl_xor_sync(0xffffffffu, s1, 2);
            ssl[mt][0] = s0; ssl[mt][1] = s1;
        }
        if (tig == 0) {
#pragma unroll
            for (int mt = 0; mt < 4; mt++) {
                int r0 = wm * 64 + mt * 16 + qid;
                rss[(r0)     * 4 + wn] = ssl[mt][0];
                rss[(r0 + 8) * 4 + wn] = ssl[mt][1];
            }
        }
        __syncthreads();   // all GEMM0 MMAs done before XA[0..63] overwrite
#pragma unroll
        for (int mt = 0; mt < 4; mt++) {
#pragma unroll
            for (int h = 0; h < 2; h++) {
                int r = wm * 64 + mt * 16 + qid + h * 8;
                float ss = rss[r * 4 + 0] + rss[r * 4 + 1] + rss[r * 4 + 2] + rss[r * 4 + 3];
                float scl = 1.0f / fmaxf(sqrtf(ss), 1e-12f);
#pragma unroll
                for (int nt = 0; nt < 4; nt++) {
                    float ox = fmaxf(acc[mt][nt][h * 2 + 0] * scl, 0.f);
                    float oy = fmaxf(acc[mt][nt][h * 2 + 1] * scl, 0.f);
                    XA[r * RSX + wn * 16 + nt * 4 + tig] = pack_h2(ox, oy);
                }
            }
        }
    }

    // ================= GEMM1: [x|h] @ wh1^T =================
    resetAcc();
    runChunks(4, 1);

    // epilogue1: +bl1, relu, h2 -> XA words 0..63
    __syncthreads();   // all GEMM1 MMAs done before overwriting h
    {
#pragma unroll
        for (int mt = 0; mt < 4; mt++) {
#pragma unroll
            for (int h = 0; h < 2; h++) {
                int r = wm * 64 + mt * 16 + qid + h * 8;
#pragma unroll
                for (int nt = 0; nt < 4; nt++) {
                    float bx = bsm[128 + wn * 32 + nt * 8 + tig * 2];
                    float by = bsm[128 + wn * 32 + nt * 8 + tig * 2 + 1];
                    float ox = fmaxf(acc[mt][nt][h * 2 + 0] + bx, 0.f);
                    float oy = fmaxf(acc[mt][nt][h * 2 + 1] + by, 0.f);
                    XA[r * RSX + wn * 16 + nt * 4 + tig] = pack_h2(ox, oy);
                }
            }
        }
    }

    // ================= GEMM2: h2 @ wh2^T =================
    resetAcc();
    runChunks(2, 2);

    // epilogue2: cols 0..63 -> t2 (half2), 64..127 -> r2 (f32)
    {
        const bool is_t2 = (wn < 2);
        const int coff0 = is_t2 ? wn * 32 : (wn - 2) * 32;
#pragma unroll
        for (int mt = 0; mt < 4; mt++) {
#pragma unroll
            for (int h = 0; h < 2; h++) {
                int gm = m0 + wm * 64 + mt * 16 + qid + h * 8;
                if (gm < NN) {
#pragma unroll
                    for (int nt = 0; nt < 4; nt++) {
                        float ox = acc[mt][nt][h * 2 + 0];
                        float oy = acc[mt][nt][h * 2 + 1];
                        if (is_t2) {
                            g_t2h[(size_t)gm * 32 + (coff0 >> 1) + nt * 4 + tig] = pack_h2(ox, oy);
                        } else {
                            *(float2*)(g_r2 + (size_t)gm * 64 + coff0 + nt * 8 + tig * 2)
                                = make_float2(ox, oy);
                        }
                    }
                }
            }
        }
    }
}

// ---------------- final: gather t2(half), unroll-8, out = norm( mean + b2 + r2 ) -------
__global__ void k_out(const float* __restrict__ b2, float* __restrict__ out) {
    int node = (blockIdx.x * blockDim.x + threadIdx.x) >> 5;
    int lane = threadIdx.x & 31;
    if (node >= NN) return;
    int beg = g_rowp[node], end = g_rowp[node + 1];
    float2 a0 = make_float2(0.f, 0.f);
    float2 a1 = make_float2(0.f, 0.f);
    float2 a2 = make_float2(0.f, 0.f);
    float2 a3 = make_float2(0.f, 0.f);
    int i = beg;
    for (; i + 7 < end; i += 8) {
        int idx[8];
#pragma unroll
        for (int q = 0; q < 8; q++) idx[q] = __ldg(&g_srcs[i + q]);
        unsigned u[8];
#pragma unroll
        for (int q = 0; q < 8; q++)
            u[q] = __ldg(&g_t2h[(size_t)idx[q] * 32 + lane]);
#pragma unroll
        for (int q = 0; q < 8; q += 4) {
            float2 v0 = h2f2(u[q+0]);
            float2 v1 = h2f2(u[q+1]);
            float2 v2 = h2f2(u[q+2]);
            float2 v3 = h2f2(u[q+3]);
            a0.x += v0.x; a0.y += v0.y;
            a1.x += v1.x; a1.y += v1.y;
            a2.x += v2.x; a2.y += v2.y;
            a3.x += v3.x; a3.y += v3.y;
        }
    }
    for (; i < end; i++) {
        int s0 = __ldg(&g_srcs[i]);
        float2 v0 = h2f2(__ldg(&g_t2h[(size_t)s0 * 32 + lane]));
        a0.x += v0.x; a0.y += v0.y;
    }
    float inv = 1.0f / fmaxf((float)(end - beg), 1.0f);
    float2 r  = ((const float2*)(g_r2 + (size_t)node * CC))[lane];
    float2 bb = ((const float2*)b2)[lane];
    float v0 = (a0.x + a1.x + a2.x + a3.x) * inv + bb.x + r.x;
    float v1 = (a0.y + a1.y + a2.y + a3.y) * inv + bb.y + r.y;
    float ss = v0 * v0 + v1 * v1;
#pragma unroll
    for (int o = 16; o >= 1; o >>= 1) ss += __shfl_xor_sync(0xffffffffu, ss, o);
    float sc = 1.0f / fmaxf(sqrtf(ss), 1e-12f);
    ((float2*)(out + (size_t)node * CC))[lane] = make_float2(v0 * sc, v1 * sc);
}

// ---------------- launch ----------------------------------------------------------------
extern "C" void kernel_launch(void* const* d_in, const int* in_sizes, int n_in,
                              void* d_out, int out_size) {
    const float* x    = (const float*)d_in[0];
    const int*   ei   = (const int*)  d_in[1];
    const float* W1_l = (const float*)d_in[2];
    const float* b1   = (const float*)d_in[3];
    const float* W1_r = (const float*)d_in[4];
    const float* Wl1  = (const float*)d_in[5];
    const float* bl1  = (const float*)d_in[6];
    const float* W2_l = (const float*)d_in[7];
    const float* b2   = (const float*)d_in[8];
    const float* W2_r = (const float*)d_in[9];
    float* out = (float*)d_out;

    static bool attr_done = false;
    if (!attr_done) {
        cudaFuncSetAttribute(k_fused, cudaFuncAttributeMaxDynamicSharedMemorySize, FUSED_SMEM);
        attr_done = true;
    }

    k_prep  <<<(NN * 32 + 255) / 256, 256>>>(x, ei, W1_l, W1_r, Wl1, W2_l, W2_r);
    k_scanA <<<SCAN_NB, 256>>>();
    k_scanC <<<SCAN_NB, 256>>>();
    k_bin   <<<(EE / 4 + 255) / 256, 256>>>(ei);
    k_aggr1 <<<(NN * 32 + 255) / 256, 256>>>();
    k_fused <<<(NN + 127) / 128, 256, FUSED_SMEM>>>(b1, bl1);
    k_out   <<<(NN * 32 + 255) / 256, 256>>>(b2, out);
}